// round 4
// baseline (speedup 1.0000x reference)
#include <cuda_runtime.h>
#include <math.h>

// CharsLstm: B=64, T=512, E=256, H=1024, V=256.
// Inputs: x[B,T] i32, emb[V,E], W_ih[4H,E], W_hh[4H,H], b_ih[4H], b_hh[4H],
//         h0[B,H], c0[B,H] (fp32). Output: final h [B,H] fp32.
//
// R4: single persistent kernel for all 512 timesteps.
//  - 128 blocks x 256 threads, 1 block/SM (170KB dynamic smem), custom grid
//    barrier between steps (co-residency guaranteed: 128 <= 148 SMs).
//  - Each block owns 8 hidden units = 32 gate rows. Its W_hh slice
//    (32x1024 = 128KB) is transposed into SMEM ONCE and reused for all steps.
//  - h kept transposed in global (g_hT[j][b]) and streamed per step through a
//    double-buffered 64-k chunk (17KB x2) via __ldcg/__stcg (L1 not coherent
//    across blocks; cg ops keep the handoff in L2).
//  - Thread tile 2 rows x 4 batches over full K: 8 FFMA per (1 LDS.64 w +
//    1 LDS.128 h); no cross-thread K reduction needed.
//  - table[v][g] = W_ih@emb[v] + b_ih + b_hh precomputed (input proj = gather).

#define BB   64
#define TT   512
#define EE   256
#define HH   1024
#define GG   4096
#define NBLK 128
#define NTHR 256
#define ROWS 32          // gate rows per block
#define JT   8           // hidden units per block
#define CHUNK 64         // k per h chunk
#define NCHUNK 16
#define HP   68          // hs pitch (floats)
#define GP   68          // gs pitch (floats)

#define WS_SZ (HH * ROWS)            // 32768 floats = 128KB
#define HS_SZ (CHUNK * HP)           // 4352 floats = 17KB
#define SMEM_FLOATS (WS_SZ + 2 * HS_SZ + ROWS * GP)
#define SMEM_BYTES (SMEM_FLOATS * 4) // 174592 B

__device__ float    g_table[256 * GG];   // 4 MB
__device__ float    g_hT[2][HH * BB];    // transposed hidden state, ping-pong
__device__ float    g_c[BB * HH];        // cell state
__device__ unsigned g_bar_cnt;
__device__ unsigned g_bar_gen;

// ---------------------------------------------------------------------------
__global__ void table_kernel(const float* __restrict__ emb,
                             const float* __restrict__ W_ih,
                             const float* __restrict__ b_ih,
                             const float* __restrict__ b_hh) {
    __shared__ float es[EE];
    const int v = blockIdx.y;
    const int g = blockIdx.x * 128 + threadIdx.x;
    for (int i = threadIdx.x; i < EE; i += 128) es[i] = emb[v * EE + i];
    __syncthreads();
    float acc = 0.f;
    if (v != 0) {
        const float* wr = W_ih + (size_t)g * EE;
#pragma unroll 8
        for (int e = 0; e < EE; e++) acc += wr[e] * es[e];
    }
    g_table[v * GG + g] = acc + b_ih[g] + b_hh[g];
}

// c init + h0 transpose + barrier reset (deterministic per launch)
__global__ void init_kernel(const float* __restrict__ h0,
                            const float* __restrict__ c0) {
    int i = blockIdx.x * 256 + threadIdx.x;   // 0..65535
    g_c[i] = c0[i];
    int b = i >> 10, j = i & (HH - 1);
    g_hT[1][j * BB + b] = h0[i];              // t=0 reads buffer (t+1)&1 = 1
    if (i == 0) { g_bar_cnt = 0; g_bar_gen = 0; }
}

// ---------------------------------------------------------------------------
__device__ __forceinline__ void grid_barrier(unsigned gen_next) {
    __syncthreads();
    if (threadIdx.x == 0) {
        __threadfence();
        unsigned a = atomicAdd(&g_bar_cnt, 1);
        if (a == NBLK - 1) {
            atomicExch(&g_bar_cnt, 0);
            __threadfence();
            atomicExch(&g_bar_gen, gen_next);
        } else {
            while (*((volatile unsigned*)&g_bar_gen) < gen_next) { }
            __threadfence();
        }
    }
    __syncthreads();
}

// ---------------------------------------------------------------------------
__global__ void __launch_bounds__(NTHR, 1)
step_all(const float* __restrict__ Whh,
         const int*   __restrict__ x,
         float*       __restrict__ out) {
    extern __shared__ float sm[];
    float* ws  = sm;                      // [k][32 rows], pitch 32
    float* hs0 = sm + WS_SZ;              // [CHUNK][HP]
    float* hs1 = hs0 + HS_SZ;
    float* gs  = hs1 + HS_SZ;             // [32 rows][GP]

    const int tid = threadIdx.x;
    const int j0  = blockIdx.x * JT;

    // ---- stage W slice once: ws[k*32 + lr] = Whh[grow(lr)*HH + k] ----
    {
        const int lr   = tid >> 3;                         // 0..31
        const int kp   = tid & 7;                          // 128 k each
        const int grow = (lr >> 3) * HH + j0 + (lr & 7);
        const float* src = Whh + (size_t)grow * HH + kp * 128;
#pragma unroll 4
        for (int u = 0; u < 32; u++) {
            float4 v = *(const float4*)(src + u * 4);
            int k = kp * 128 + u * 4;
            ws[(k + 0) * ROWS + lr] = v.x;
            ws[(k + 1) * ROWS + lr] = v.y;
            ws[(k + 2) * ROWS + lr] = v.z;
            ws[(k + 3) * ROWS + lr] = v.w;
        }
    }
    __syncthreads();

    const int rg = tid >> 4;      // 0..15 -> rows 2rg, 2rg+1
    const int bg = tid & 15;      // 0..15 -> batches 4bg..4bg+3
    const int hr = tid >> 2;      // 0..63  (chunk-load row)
    const int hq = (tid & 3) * 16;

    for (int t = 0; t < TT; t++) {
        const float* __restrict__ hprev = g_hT[(t + 1) & 1];

        float a0=0,a1=0,a2=0,a3=0,a4=0,a5=0,a6=0,a7=0;

        // prologue: chunk 0 -> hs0
        float4 p0, p1, p2, p3;
        {
            const float* s = hprev + hr * BB + hq;
            p0 = __ldcg((const float4*)(s));
            p1 = __ldcg((const float4*)(s + 4));
            p2 = __ldcg((const float4*)(s + 8));
            p3 = __ldcg((const float4*)(s + 12));
            float* d = hs0 + hr * HP + hq;
            *(float4*)(d)      = p0;
            *(float4*)(d + 4)  = p1;
            *(float4*)(d + 8)  = p2;
            *(float4*)(d + 12) = p3;
        }
        __syncthreads();

#pragma unroll 1
        for (int c = 0; c < NCHUNK; c++) {
            // prefetch next chunk
            if (c + 1 < NCHUNK) {
                const float* s = hprev + (c + 1) * (CHUNK * BB) + hr * BB + hq;
                p0 = __ldcg((const float4*)(s));
                p1 = __ldcg((const float4*)(s + 4));
                p2 = __ldcg((const float4*)(s + 8));
                p3 = __ldcg((const float4*)(s + 12));
            }
            // compute on current buffer
            const float* hb = (c & 1) ? hs1 : hs0;
            const float* wp = ws + c * (CHUNK * ROWS) + 2 * rg;
            const float* hp = hb + 4 * bg;
#pragma unroll 16
            for (int kk = 0; kk < CHUNK; kk++) {
                float2 wv = *(const float2*)(wp);  wp += ROWS;
                float4 hv = *(const float4*)(hp);  hp += HP;
                a0 += wv.x * hv.x; a1 += wv.x * hv.y;
                a2 += wv.x * hv.z; a3 += wv.x * hv.w;
                a4 += wv.y * hv.x; a5 += wv.y * hv.y;
                a6 += wv.y * hv.z; a7 += wv.y * hv.w;
            }
            // store prefetched chunk into the other buffer
            if (c + 1 < NCHUNK) {
                float* d = (((c + 1) & 1) ? hs1 : hs0) + hr * HP + hq;
                *(float4*)(d)      = p0;
                *(float4*)(d + 4)  = p1;
                *(float4*)(d + 8)  = p2;
                *(float4*)(d + 12) = p3;
            }
            __syncthreads();
        }

        // ---- stash gates in smem ----
        {
            float* g0 = gs + (2 * rg) * GP + 4 * bg;
            *(float4*)g0 = make_float4(a0, a1, a2, a3);
            float* g1 = gs + (2 * rg + 1) * GP + 4 * bg;
            *(float4*)g1 = make_float4(a4, a5, a6, a7);
        }
        __syncthreads();

        // ---- fused LSTM cell: 512 (jj,b) pairs, 2 per thread ----
        float* __restrict__ hnext = g_hT[t & 1];
#pragma unroll
        for (int q = 0; q < 2; q++) {
            int idx = q * NTHR + tid;      // 0..511
            int jj  = idx & 7;
            int b   = idx >> 3;
            int tok = x[b * TT + t];
            const float* tb = g_table + (size_t)tok * GG + j0 + jj;
            float ipre = gs[(0 * 8 + jj) * GP + b] + tb[0];
            float fpre = gs[(1 * 8 + jj) * GP + b] + tb[HH];
            float gpre = gs[(2 * 8 + jj) * GP + b] + tb[2 * HH];
            float opre = gs[(3 * 8 + jj) * GP + b] + tb[3 * HH];
            float isg = 1.f / (1.f + expf(-ipre));
            float fsg = 1.f / (1.f + expf(-fpre));
            float gth = tanhf(gpre);
            float osg = 1.f / (1.f + expf(-opre));
            int ci = b * HH + j0 + jj;
            float cv = fsg * g_c[ci] + isg * gth;
            g_c[ci] = cv;
            float hval = osg * tanhf(cv);
            if (t == TT - 1) out[ci] = hval;
            else __stcg(&hnext[(j0 + jj) * BB + b], hval);
        }

        if (t < TT - 1) grid_barrier((unsigned)(t + 1));
    }
}

// ---------------------------------------------------------------------------
extern "C" void kernel_launch(void* const* d_in, const int* in_sizes, int n_in,
                              void* d_out, int out_size) {
    const int*   x   = (const int*)  d_in[0];
    const float* emb = (const float*)d_in[1];
    const float* Wih = (const float*)d_in[2];
    const float* Whh = (const float*)d_in[3];
    const float* bih = (const float*)d_in[4];
    const float* bhh = (const float*)d_in[5];
    const float* h0  = (const float*)d_in[6];
    const float* c0  = (const float*)d_in[7];
    float*       out = (float*)d_out;

    static int attr_set = 0;
    if (!attr_set) {
        cudaFuncSetAttribute(step_all,
                             cudaFuncAttributeMaxDynamicSharedMemorySize,
                             SMEM_BYTES);
        attr_set = 1;
    }

    table_kernel<<<dim3(GG / 128, 256), 128>>>(emb, Wih, bih, bhh);
    init_kernel<<<(BB * HH) / 256, 256>>>(h0, c0);
    step_all<<<NBLK, NTHR, SMEM_BYTES>>>(Whh, x, out);
}

// round 6
// speedup vs baseline: 2.3931x; 2.3931x over previous
#include <cuda_runtime.h>
#include <cuda_bf16.h>
#include <math.h>
#include <stdint.h>

// CharsLstm B=64 T=512 E=256 H=1024 V=256 — mma.sync bf16 split-precision.
//
// gates[4096,64] = W @ h with W,h split hi/lo in bf16:
//   W*h ~= Whi*hhi + Wlo*hhi + Whi*hlo      (lo*lo dropped, ~2^-16/term)
//
// 128 persistent blocks (1/SM), 256 thr. Block owns 32 gate rows =
// 8 hidden units x 4 gates. Whi/Wlo (32x1024 bf16 each) resident in SMEM for
// all 512 steps. h ping-pong in global as bf16 [batch][k] (hi & lo planes),
// streamed per step via cp.async.cg in 16KB double-buffered chunks.
// GEMM: mma.sync.m16n8k16 bf16 (warp tile m16 x n16, 2x4 warps).
// Cell state c in registers. Grid barrier between steps.

#define BB   64
#define TT   512
#define HH   1024
#define GG   4096
#define NBLK 128
#define NTHR 256

#define WP_B   2064                   // W smem row pitch bytes (1032 bf16)
#define HP_B   272                    // h chunk row pitch bytes (136 bf16)
#define OFF_TOK 0
#define OFF_GS  256
#define OFF_WHI 8704                  // 256 + 32*66*4 = 8704
#define OFF_WLO (OFF_WHI + 32 * WP_B)         // +66048
#define OFF_HS0 (OFF_WLO + 32 * WP_B)
#define OFF_HS1 (OFF_HS0 + 64 * HP_B)         // 17408 each
#define SMEM_BYTES (OFF_HS1 + 64 * HP_B)      // 175616

__device__ __nv_bfloat16 g_Whi[GG * HH];          // 8 MB
__device__ __nv_bfloat16 g_Wlo[GG * HH];          // 8 MB
__device__ __nv_bfloat16 g_h[2][2][BB * HH];      // [ping][hi/lo][b*1024+k]
__device__ float    g_table[256 * GG];            // 4 MB
__device__ unsigned g_bar_cnt;
__device__ unsigned g_bar_gen;

// ---------------------------------------------------------------- helpers
__device__ __forceinline__ uint32_t smem_u32(const void* p) {
    uint32_t a;
    asm("{ .reg .u64 t; cvta.to.shared.u64 t, %1; cvt.u32.u64 %0, t; }"
        : "=r"(a) : "l"(p));
    return a;
}
#define LDSM4(r0, r1, r2, r3, a)                                            \
    asm volatile("ldmatrix.sync.aligned.m8n8.x4.shared.b16 {%0,%1,%2,%3}, [%4];" \
        : "=r"(r0), "=r"(r1), "=r"(r2), "=r"(r3) : "r"(a))
#define MMA16816(d0, d1, d2, d3, a0, a1, a2, a3, b0, b1)                    \
    asm volatile("mma.sync.aligned.m16n8k16.row.col.f32.bf16.bf16.f32 "     \
        "{%0,%1,%2,%3}, {%4,%5,%6,%7}, {%8,%9}, {%0,%1,%2,%3};"             \
        : "+f"(d0), "+f"(d1), "+f"(d2), "+f"(d3)                            \
        : "r"(a0), "r"(a1), "r"(a2), "r"(a3), "r"(b0), "r"(b1))
#define CP_ASYNC16(dst, src)                                                \
    asm volatile("cp.async.cg.shared.global [%0], [%1], 16;"                \
        :: "r"(dst), "l"(src) : "memory")
#define CP_COMMIT() asm volatile("cp.async.commit_group;" ::: "memory")
#define CP_WAIT0()  asm volatile("cp.async.wait_group 0;" ::: "memory")

// ---------------------------------------------------------------- setup
// table[v][g] = (v?dot(emb[v],W_ih[g]):0) + b_ih[g] + b_hh[g]
__global__ void table_kernel(const float* __restrict__ emb,
                             const float* __restrict__ W_ih,
                             const float* __restrict__ b_ih,
                             const float* __restrict__ b_hh) {
    __shared__ float embs[32 * 65];
    __shared__ float wch[64 * 129];
    const int g  = threadIdx.x;
    const int gt = blockIdx.x, vt = blockIdx.y;
    float acc[32];
#pragma unroll
    for (int v = 0; v < 32; v++) acc[v] = 0.f;

    for (int ch = 0; ch < 4; ch++) {
        __syncthreads();
        for (int i = g; i < 2048; i += 128) {
            int v = i >> 6, e = i & 63;
            embs[v * 65 + e] = emb[(vt * 32 + v) * 256 + ch * 64 + e];
        }
        {
            const float4* src = (const float4*)(W_ih + (size_t)(gt * 128 + g) * 256 + ch * 64);
#pragma unroll
            for (int q = 0; q < 16; q++) {
                float4 w = src[q];
                wch[(q * 4 + 0) * 129 + g] = w.x;
                wch[(q * 4 + 1) * 129 + g] = w.y;
                wch[(q * 4 + 2) * 129 + g] = w.z;
                wch[(q * 4 + 3) * 129 + g] = w.w;
            }
        }
        __syncthreads();
#pragma unroll 4
        for (int e = 0; e < 64; e++) {
            float w = wch[e * 129 + g];
#pragma unroll
            for (int v = 0; v < 32; v++) acc[v] += w * embs[v * 65 + e];
        }
    }
    int col = gt * 128 + g;
    float bias = b_ih[col] + b_hh[col];
#pragma unroll
    for (int v = 0; v < 32; v++) {
        int tok = vt * 32 + v;
        g_table[(size_t)tok * GG + col] = (tok == 0 ? 0.f : acc[v]) + bias;
    }
}

// W -> bf16 hi/lo planes (coalesced, layout unchanged: [row 4096][k 1024])
__global__ void pack_w_kernel(const float* __restrict__ Whh) {
    int idx = blockIdx.x * 256 + threadIdx.x;       // < 4096*1024
    float v = Whh[idx];
    __nv_bfloat16 hi = __float2bfloat16(v);
    g_Whi[idx] = hi;
    g_Wlo[idx] = __float2bfloat16(v - __bfloat162float(hi));
}

// h0 -> bf16 hi/lo [b][k] (t=0 reads ping (0+1)&1 = 1); barrier reset
__global__ void init_kernel(const float* __restrict__ h0) {
    int i = blockIdx.x * 256 + threadIdx.x;         // 0..65535
    float v = h0[i];
    __nv_bfloat16 hi = __float2bfloat16(v);
    g_h[1][0][i] = hi;
    g_h[1][1][i] = __float2bfloat16(v - __bfloat162float(hi));
    if (i == 0) { g_bar_cnt = 0; g_bar_gen = 0; }
}

// ---------------------------------------------------------------- barrier
__device__ __forceinline__ void grid_barrier(unsigned gen_next) {
    __threadfence();
    __syncthreads();
    if (threadIdx.x == 0) {
        unsigned a = atomicAdd(&g_bar_cnt, 1);
        if (a == NBLK - 1) {
            atomicExch(&g_bar_cnt, 0);
            __threadfence();
            atomicExch(&g_bar_gen, gen_next);
        } else {
            while (*((volatile unsigned*)&g_bar_gen) < gen_next) { }
            __threadfence();
        }
    }
    __syncthreads();
}

// ---------------------------------------------------------------- main
__global__ void __launch_bounds__(NTHR, 1)
step_all(const int* __restrict__ x,
         const float* __restrict__ c0,
         float* __restrict__ out) {
    extern __shared__ __align__(16) unsigned char sm[];
    const uint32_t smb = smem_u32(sm);
    int*   s_tok = (int*)(sm + OFF_TOK);
    float* gs    = (float*)(sm + OFF_GS);     // [32 rows][pitch 66]

    const int tid  = threadIdx.x;
    const int bid  = blockIdx.x;
    const int lane = tid & 31;
    const int warp = tid >> 5;
    const int warpM = warp & 1;               // 2 x m16
    const int warpN = warp >> 1;              // 4 x n16

    // ---- stage Whi/Wlo slices once (block rows: gate*8 + jj) ----
    {
#pragma unroll
        for (int j = 0; j < 16; j++) {
            int i = j * 256 + tid;            // 4096 float4 per plane
            int row = i >> 7, q = i & 127;
            int grow = (row >> 3) * HH + bid * 8 + (row & 7);
            *(float4*)(sm + OFF_WHI + row * WP_B + q * 16) =
                __ldcg((const float4*)(g_Whi + (size_t)grow * HH) + q);
            *(float4*)(sm + OFF_WLO + row * WP_B + q * 16) =
                __ldcg((const float4*)(g_Wlo + (size_t)grow * HH) + q);
        }
    }

    // ---- per-lane ldmatrix address bases ----
    // A (m16k16): lanes 0-15 -> rows, lanes 16-31 -> +8 k offset
    const int rowA  = warpM * 16 + (lane & 15);
    const int kOffA = (lane >> 4) * 8;
    const uint32_t aHiBase = smb + OFF_WHI + rowA * WP_B + kOffA * 2;
    const uint32_t aLoBase = smb + OFF_WLO + rowA * WP_B + kOffA * 2;
    // B (k16n16 from BT[n][k]): n = warpN*16 + ((lane>>4)&1)*8 + (lane&7)
    const int nB    = warpN * 16 + ((lane >> 4) & 1) * 8 + (lane & 7);
    const int kOffB = ((lane >> 3) & 1) * 8;
    const uint32_t bBase0 = smb + OFF_HS0 + nB * HP_B + kOffB * 2;
    const uint32_t bBase1 = smb + OFF_HS1 + nB * HP_B + kOffB * 2;

    // chunk-copy indices: 4 x cp.async(16B) per thread per 16KB chunk
    const int crow = tid >> 4;                // 0..15 (+16 per iter)
    const int ck   = (tid & 15) * 8;          // bf16 offset in 128-k chunk

    // cell-epilogue mapping & persistent cell state
    float creg[2];
#pragma unroll
    for (int q = 0; q < 2; q++) {
        int idx = q * NTHR + tid;
        int jj = idx & 7, b = idx >> 3;
        creg[q] = c0[b * HH + bid * 8 + jj];
    }

    __syncthreads();

#pragma unroll 1
    for (int t = 0; t < TT; t++) {
        const __nv_bfloat16* __restrict__ hhi = g_h[(t + 1) & 1][0];
        const __nv_bfloat16* __restrict__ hlo = g_h[(t + 1) & 1][1];
        if (tid < BB) s_tok[tid] = x[tid * TT + t];

        float d00=0,d01=0,d02=0,d03=0, d10=0,d11=0,d12=0,d13=0;

        // prefetch chunk 0 (hhi k0..127) -> hs0
        {
            const __nv_bfloat16* src = hhi + crow * HH + ck;
            uint32_t dst = smb + OFF_HS0 + crow * HP_B + ck * 2;
#pragma unroll
            for (int it = 0; it < 4; it++)
                CP_ASYNC16(dst + it * 16 * HP_B, src + it * 16 * HH);
            CP_COMMIT();
        }

        // 16 chunks: 0-7 = hhi (4-mma), 8-15 = hlo (2-mma)
#pragma unroll 1
        for (int c = 0; c < 16; c++) {
            CP_WAIT0();
            __syncthreads();
            if (c < 15) {   // prefetch next chunk into other buffer
                const __nv_bfloat16* plane = (c + 1 < 8) ? hhi : hlo;
                const __nv_bfloat16* src = plane + crow * HH + ((c + 1) & 7) * 128 + ck;
                uint32_t dst = (((c + 1) & 1) ? (smb + OFF_HS1) : (smb + OFF_HS0))
                               + crow * HP_B + ck * 2;
#pragma unroll
                for (int it = 0; it < 4; it++)
                    CP_ASYNC16(dst + it * 16 * HP_B, src + it * 16 * HH);
                CP_COMMIT();
            }
            const uint32_t bB = (c & 1) ? bBase1 : bBase0;
            const uint32_t aOff = (c & 7) * 256;    // c8*128 k * 2B
            if (c < 8) {
#pragma unroll
                for (int s = 0; s < 8; s++) {
                    uint32_t ahi0,ahi1,ahi2,ahi3, alo0,alo1,alo2,alo3, b0,b1,b2,b3;
                    LDSM4(ahi0,ahi1,ahi2,ahi3, aHiBase + aOff + s * 32);
                    LDSM4(alo0,alo1,alo2,alo3, aLoBase + aOff + s * 32);
                    LDSM4(b0,b1,b2,b3, bB + s * 32);
                    MMA16816(d00,d01,d02,d03, ahi0,ahi1,ahi2,ahi3, b0,b1);
                    MMA16816(d00,d01,d02,d03, alo0,alo1,alo2,alo3, b0,b1);
                    MMA16816(d10,d11,d12,d13, ahi0,ahi1,ahi2,ahi3, b2,b3);
                    MMA16816(d10,d11,d12,d13, alo0,alo1,alo2,alo3, b2,b3);
                }
            } else {
#pragma unroll
                for (int s = 0; s < 8; s++) {
                    uint32_t a0,a1,a2,a3, b0,b1,b2,b3;
                    LDSM4(a0,a1,a2,a3, aHiBase + aOff + s * 32);
                    LDSM4(b0,b1,b2,b3, bB + s * 32);
                    MMA16816(d00,d01,d02,d03, a0,a1,a2,a3, b0,b1);
                    MMA16816(d10,d11,d12,d13, a0,a1,a2,a3, b2,b3);
                }
            }
        }

        // ---- accum frags -> gs[row][b] (pitch 66) ----
        __syncthreads();   // chunk buffers idle; gs writes safe vs prior reads
        {
            const int r0 = warpM * 16 + (lane >> 2);
            const int c0i = warpN * 16 + (lane & 3) * 2;
            *(float2*)(gs + (r0    ) * 66 + c0i    ) = make_float2(d00, d01);
            *(float2*)(gs + (r0 + 8) * 66 + c0i    ) = make_float2(d02, d03);
            *(float2*)(gs + (r0    ) * 66 + c0i + 8) = make_float2(d10, d11);
            *(float2*)(gs + (r0 + 8) * 66 + c0i + 8) = make_float2(d12, d13);
        }
        __syncthreads();

        // ---- fused LSTM cell: 2 cells/thread ----
        __nv_bfloat16* __restrict__ nhi = g_h[t & 1][0];
        __nv_bfloat16* __restrict__ nlo = g_h[t & 1][1];
#pragma unroll
        for (int q = 0; q < 2; q++) {
            int idx = q * NTHR + tid;
            int jj = idx & 7, b = idx >> 3;
            int J = bid * 8 + jj;
            int tok = s_tok[b];
            const float* trow = g_table + (size_t)tok * GG + J;
            float ipre = gs[(0 * 8 + jj) * 66 + b] + trow[0];
            float fpre = gs[(1 * 8 + jj) * 66 + b] + trow[HH];
            float gpre = gs[(2 * 8 + jj) * 66 + b] + trow[2 * HH];
            float opre = gs[(3 * 8 + jj) * 66 + b] + trow[3 * HH];
            float isg = 1.f / (1.f + expf(-ipre));
            float fsg = 1.f / (1.f + expf(-fpre));
            float gth = tanhf(gpre);
            float osg = 1.f / (1.f + expf(-opre));
            float cv = fsg * creg[q] + isg * gth;
            creg[q] = cv;
            float hv = osg * tanhf(cv);
            __nv_bfloat16 hi = __float2bfloat16(hv);
            nhi[b * HH + J] = hi;
            nlo[b * HH + J] = __float2bfloat16(hv - __bfloat162float(hi));
            if (t == TT - 1) out[b * HH + J] = hv;
        }

        if (t < TT - 1) grid_barrier((unsigned)(t + 1));
    }
}

// ---------------------------------------------------------------------------
extern "C" void kernel_launch(void* const* d_in, const int* in_sizes, int n_in,
                              void* d_out, int out_size) {
    const int*   x   = (const int*)  d_in[0];
    const float* emb = (const float*)d_in[1];
    const float* Wih = (const float*)d_in[2];
    const float* Whh = (const float*)d_in[3];
    const float* bih = (const float*)d_in[4];
    const float* bhh = (const float*)d_in[5];
    const float* h0  = (const float*)d_in[6];
    const float* c0  = (const float*)d_in[7];
    float*       out = (float*)d_out;

    static int attr_set = 0;
    if (!attr_set) {
        cudaFuncSetAttribute(step_all,
                             cudaFuncAttributeMaxDynamicSharedMemorySize,
                             SMEM_BYTES);
        attr_set = 1;
    }

    table_kernel<<<dim3(32, 8), 128>>>(emb, Wih, bih, bhh);
    pack_w_kernel<<<(GG * HH) / 256, 256>>>(Whh);
    init_kernel<<<(BB * HH) / 256, 256>>>(h0);
    step_all<<<NBLK, NTHR, SMEM_BYTES>>>(x, c0, out);
}

// round 7
// speedup vs baseline: 2.7510x; 1.1495x over previous
#include <cuda_runtime.h>
#include <cuda_bf16.h>
#include <math.h>
#include <stdint.h>

// CharsLstm B=64 T=512 E=256 H=1024 V=256 — mma.sync bf16 split-precision.
//
// gates[4096,64] = W @ h with W,h split hi/lo in bf16:
//   W*h ~= Whi*hhi + Wlo*hhi + Whi*hlo      (lo*lo dropped, ~2^-16/term)
//
// R7: 128 persistent blocks (1/SM) x 512 threads (16 warps).
// Block owns 32 gate rows = 8 hidden units x 4 gates. Whi/Wlo (32x1024 bf16
// each) resident in SMEM all 512 steps. h ping-pong in global bf16 [b][k]
// hi/lo planes, streamed via cp.async.cg in 8 double-buffered 32KB chunks
// (256 k each). 8 output tiles m16n16, each computed by TWO warps split
// along K (warpK halves of each chunk); partials reduced through smem.
// Cell state c in registers. Grid barrier between steps.

#define BB   64
#define TT   512
#define HH   1024
#define GG   4096
#define NBLK 128
#define NTHR 512

#define WP_B   2064                   // W smem row pitch bytes (1032 bf16)
#define HP_B   528                    // h chunk row pitch bytes (264 bf16)
#define OFF_TOK 0
#define OFF_GS  256
#define OFF_WHI 8704                  // 256 + 32*66*4
#define OFF_WLO (OFF_WHI + 32 * WP_B)
#define OFF_HS0 (OFF_WLO + 32 * WP_B)         // 140800
#define OFF_HS1 (OFF_HS0 + 64 * HP_B)         // +33792
#define SMEM_BYTES (OFF_HS1 + 64 * HP_B)      // 208384

__device__ __nv_bfloat16 g_Whi[GG * HH];          // 8 MB
__device__ __nv_bfloat16 g_Wlo[GG * HH];          // 8 MB
__device__ __nv_bfloat16 g_h[2][2][BB * HH];      // [ping][hi/lo][b*1024+k]
__device__ float    g_table[256 * GG];            // 4 MB
__device__ unsigned g_bar_cnt;
__device__ unsigned g_bar_gen;

// ---------------------------------------------------------------- helpers
__device__ __forceinline__ uint32_t smem_u32(const void* p) {
    uint32_t a;
    asm("{ .reg .u64 t; cvta.to.shared.u64 t, %1; cvt.u32.u64 %0, t; }"
        : "=r"(a) : "l"(p));
    return a;
}
#define LDSM4(r0, r1, r2, r3, a)                                            \
    asm volatile("ldmatrix.sync.aligned.m8n8.x4.shared.b16 {%0,%1,%2,%3}, [%4];" \
        : "=r"(r0), "=r"(r1), "=r"(r2), "=r"(r3) : "r"(a))
#define MMA16816(d0, d1, d2, d3, a0, a1, a2, a3, b0, b1)                    \
    asm volatile("mma.sync.aligned.m16n8k16.row.col.f32.bf16.bf16.f32 "     \
        "{%0,%1,%2,%3}, {%4,%5,%6,%7}, {%8,%9}, {%0,%1,%2,%3};"             \
        : "+f"(d0), "+f"(d1), "+f"(d2), "+f"(d3)                            \
        : "r"(a0), "r"(a1), "r"(a2), "r"(a3), "r"(b0), "r"(b1))
#define CP_ASYNC16(dst, src)                                                \
    asm volatile("cp.async.cg.shared.global [%0], [%1], 16;"                \
        :: "r"(dst), "l"(src) : "memory")
#define CP_COMMIT() asm volatile("cp.async.commit_group;" ::: "memory")
#define CP_WAIT0()  asm volatile("cp.async.wait_group 0;" ::: "memory")

// ---------------------------------------------------------------- setup
__global__ void table_kernel(const float* __restrict__ emb,
                             const float* __restrict__ W_ih,
                             const float* __restrict__ b_ih,
                             const float* __restrict__ b_hh) {
    __shared__ float embs[32 * 65];
    __shared__ float wch[64 * 129];
    const int g  = threadIdx.x;
    const int gt = blockIdx.x, vt = blockIdx.y;
    float acc[32];
#pragma unroll
    for (int v = 0; v < 32; v++) acc[v] = 0.f;

    for (int ch = 0; ch < 4; ch++) {
        __syncthreads();
        for (int i = g; i < 2048; i += 128) {
            int v = i >> 6, e = i & 63;
            embs[v * 65 + e] = emb[(vt * 32 + v) * 256 + ch * 64 + e];
        }
        {
            const float4* src = (const float4*)(W_ih + (size_t)(gt * 128 + g) * 256 + ch * 64);
#pragma unroll
            for (int q = 0; q < 16; q++) {
                float4 w = src[q];
                wch[(q * 4 + 0) * 129 + g] = w.x;
                wch[(q * 4 + 1) * 129 + g] = w.y;
                wch[(q * 4 + 2) * 129 + g] = w.z;
                wch[(q * 4 + 3) * 129 + g] = w.w;
            }
        }
        __syncthreads();
#pragma unroll 4
        for (int e = 0; e < 64; e++) {
            float w = wch[e * 129 + g];
#pragma unroll
            for (int v = 0; v < 32; v++) acc[v] += w * embs[v * 65 + e];
        }
    }
    int col = gt * 128 + g;
    float bias = b_ih[col] + b_hh[col];
#pragma unroll
    for (int v = 0; v < 32; v++) {
        int tok = vt * 32 + v;
        g_table[(size_t)tok * GG + col] = (tok == 0 ? 0.f : acc[v]) + bias;
    }
}

__global__ void pack_w_kernel(const float* __restrict__ Whh) {
    int idx = blockIdx.x * 256 + threadIdx.x;
    float v = Whh[idx];
    __nv_bfloat16 hi = __float2bfloat16(v);
    g_Whi[idx] = hi;
    g_Wlo[idx] = __float2bfloat16(v - __bfloat162float(hi));
}

__global__ void init_kernel(const float* __restrict__ h0) {
    int i = blockIdx.x * 256 + threadIdx.x;
    float v = h0[i];
    __nv_bfloat16 hi = __float2bfloat16(v);
    g_h[1][0][i] = hi;
    g_h[1][1][i] = __float2bfloat16(v - __bfloat162float(hi));
    if (i == 0) { g_bar_cnt = 0; g_bar_gen = 0; }
}

// ---------------------------------------------------------------- barrier
__device__ __forceinline__ void grid_barrier(unsigned gen_next) {
    __threadfence();
    __syncthreads();
    if (threadIdx.x == 0) {
        unsigned a = atomicAdd(&g_bar_cnt, 1);
        if (a == NBLK - 1) {
            atomicExch(&g_bar_cnt, 0);
            __threadfence();
            atomicExch(&g_bar_gen, gen_next);
        } else {
            while (*((volatile unsigned*)&g_bar_gen) < gen_next) { }
            __threadfence();
        }
    }
    __syncthreads();
}

// ---------------------------------------------------------------- main
__global__ void __launch_bounds__(NTHR, 1)
step_all(const int* __restrict__ x,
         const float* __restrict__ c0,
         float* __restrict__ out) {
    extern __shared__ __align__(16) unsigned char sm[];
    const uint32_t smb = smem_u32(sm);
    int*   s_tok = (int*)(sm + OFF_TOK);
    float* gs    = (float*)(sm + OFF_GS);     // [32 rows][pitch 66]

    const int tid   = threadIdx.x;
    const int bid   = blockIdx.x;
    const int lane  = tid & 31;
    const int warp  = tid >> 5;
    const int warpM = warp & 1;               // 2 x m16
    const int warpN = (warp >> 1) & 3;        // 4 x n16
    const int warpK = warp >> 3;              // 2-way split-K
    const int khalf2 = warpK * 256;           // byte offset of k-half (128k*2B)

    // ---- stage Whi/Wlo slices once (block rows: gate*8 + jj) ----
#pragma unroll
    for (int j = 0; j < 8; j++) {
        int i = j * NTHR + tid;               // 4096 float4 per plane
        int row = i >> 7, q = i & 127;
        int grow = (row >> 3) * HH + bid * 8 + (row & 7);
        *(float4*)(sm + OFF_WHI + row * WP_B + q * 16) =
            __ldcg((const float4*)(g_Whi + (size_t)grow * HH) + q);
        *(float4*)(sm + OFF_WLO + row * WP_B + q * 16) =
            __ldcg((const float4*)(g_Wlo + (size_t)grow * HH) + q);
    }

    // ---- per-lane ldmatrix address bases ----
    const int rowA  = warpM * 16 + (lane & 15);
    const int kOffA = (lane >> 4) * 8;
    const uint32_t aHiBase = smb + OFF_WHI + rowA * WP_B + kOffA * 2 + khalf2;
    const uint32_t aLoBase = smb + OFF_WLO + rowA * WP_B + kOffA * 2 + khalf2;
    const int nB    = warpN * 16 + ((lane >> 4) & 1) * 8 + (lane & 7);
    const int kOffB = ((lane >> 3) & 1) * 8;
    const uint32_t bBase0 = smb + OFF_HS0 + nB * HP_B + kOffB * 2 + khalf2;
    const uint32_t bBase1 = smb + OFF_HS1 + nB * HP_B + kOffB * 2 + khalf2;

    // cell state: 1 cell per thread (unit jj, batch b)
    const int jj = tid & 7, bb = tid >> 3;
    float creg = c0[bb * HH + bid * 8 + jj];
    const int J = bid * 8 + jj;

    __syncthreads();

#pragma unroll 1
    for (int t = 0; t < TT; t++) {
        const __nv_bfloat16* __restrict__ hhi = g_h[(t + 1) & 1][0];
        const __nv_bfloat16* __restrict__ hlo = g_h[(t + 1) & 1][1];
        if (tid < BB) s_tok[tid] = x[tid * TT + t];

        float d00=0,d01=0,d02=0,d03=0, d10=0,d11=0,d12=0,d13=0;

        // prefetch chunk 0 (hhi k 0..255) -> hs0 : 2048 float4, 4/thread
        {
#pragma unroll
            for (int p = 0; p < 4; p++) {
                int i = p * NTHR + tid;
                int row = i >> 5, kq = i & 31;
                CP_ASYNC16(smb + OFF_HS0 + row * HP_B + kq * 16,
                           hhi + row * HH + kq * 8);
            }
            CP_COMMIT();
        }

        // 8 chunks of 256 k: 0-3 = hhi (dual MMA), 4-7 = hlo (single)
#pragma unroll 1
        for (int c = 0; c < 8; c++) {
            CP_WAIT0();
            __syncthreads();
            if (c < 7) {
                const __nv_bfloat16* plane = (c + 1 < 4) ? hhi : hlo;
                const __nv_bfloat16* src = plane + ((c + 1) & 3) * 256;
                uint32_t dst = ((c + 1) & 1) ? (smb + OFF_HS1) : (smb + OFF_HS0);
#pragma unroll
                for (int p = 0; p < 4; p++) {
                    int i = p * NTHR + tid;
                    int row = i >> 5, kq = i & 31;
                    CP_ASYNC16(dst + row * HP_B + kq * 16,
                               src + row * HH + kq * 8);
                }
                CP_COMMIT();
            }
            const uint32_t bB = (c & 1) ? bBase1 : bBase0;
            const uint32_t aOff = (uint32_t)(c & 3) * 512;   // 256 k * 2B
            if (c < 4) {
#pragma unroll
                for (int s = 0; s < 8; s++) {
                    uint32_t ahi0,ahi1,ahi2,ahi3, alo0,alo1,alo2,alo3, b0,b1,b2,b3;
                    LDSM4(ahi0,ahi1,ahi2,ahi3, aHiBase + aOff + s * 32);
                    LDSM4(alo0,alo1,alo2,alo3, aLoBase + aOff + s * 32);
                    LDSM4(b0,b1,b2,b3, bB + s * 32);
                    MMA16816(d00,d01,d02,d03, ahi0,ahi1,ahi2,ahi3, b0,b1);
                    MMA16816(d00,d01,d02,d03, alo0,alo1,alo2,alo3, b0,b1);
                    MMA16816(d10,d11,d12,d13, ahi0,ahi1,ahi2,ahi3, b2,b3);
                    MMA16816(d10,d11,d12,d13, alo0,alo1,alo2,alo3, b2,b3);
                }
            } else {
#pragma unroll
                for (int s = 0; s < 8; s++) {
                    uint32_t a0,a1,a2,a3, b0,b1,b2,b3;
                    LDSM4(a0,a1,a2,a3, aHiBase + aOff + s * 32);
                    LDSM4(b0,b1,b2,b3, bB + s * 32);
                    MMA16816(d00,d01,d02,d03, a0,a1,a2,a3, b0,b1);
                    MMA16816(d10,d11,d12,d13, a0,a1,a2,a3, b2,b3);
                }
            }
        }

        // ---- split-K reduce into gs[row][b]: warpK=1 stores, warpK=0 adds ----
        const int r0  = warpM * 16 + (lane >> 2);
        const int c0i = warpN * 16 + (lane & 3) * 2;
        if (warpK == 1) {
            *(float2*)(gs + (r0    ) * 66 + c0i    ) = make_float2(d00, d01);
            *(float2*)(gs + (r0 + 8) * 66 + c0i    ) = make_float2(d02, d03);
            *(float2*)(gs + (r0    ) * 66 + c0i + 8) = make_float2(d10, d11);
            *(float2*)(gs + (r0 + 8) * 66 + c0i + 8) = make_float2(d12, d13);
        }
        __syncthreads();
        if (warpK == 0) {
            float2* p;
            p = (float2*)(gs + (r0    ) * 66 + c0i    ); p->x += d00; p->y += d01;
            p = (float2*)(gs + (r0 + 8) * 66 + c0i    ); p->x += d02; p->y += d03;
            p = (float2*)(gs + (r0    ) * 66 + c0i + 8); p->x += d10; p->y += d11;
            p = (float2*)(gs + (r0 + 8) * 66 + c0i + 8); p->x += d12; p->y += d13;
        }
        __syncthreads();

        // ---- fused LSTM cell: 1 cell per thread ----
        __nv_bfloat16* __restrict__ nhi = g_h[t & 1][0];
        __nv_bfloat16* __restrict__ nlo = g_h[t & 1][1];
        {
            int tok = s_tok[bb];
            const float* trow = g_table + (size_t)tok * GG + J;
            float ipre = gs[(0 * 8 + jj) * 66 + bb] + trow[0];
            float fpre = gs[(1 * 8 + jj) * 66 + bb] + trow[HH];
            float gpre = gs[(2 * 8 + jj) * 66 + bb] + trow[2 * HH];
            float opre = gs[(3 * 8 + jj) * 66 + bb] + trow[3 * HH];
            float isg = 1.f / (1.f + expf(-ipre));
            float fsg = 1.f / (1.f + expf(-fpre));
            float gth = tanhf(gpre);
            float osg = 1.f / (1.f + expf(-opre));
            float cv = fsg * creg + isg * gth;
            creg = cv;
            float hv = osg * tanhf(cv);
            __nv_bfloat16 hi = __float2bfloat16(hv);
            nhi[bb * HH + J] = hi;
            nlo[bb * HH + J] = __float2bfloat16(hv - __bfloat162float(hi));
            if (t == TT - 1) out[bb * HH + J] = hv;
        }

        if (t < TT - 1) grid_barrier((unsigned)(t + 1));
    }
}

// ---------------------------------------------------------------------------
extern "C" void kernel_launch(void* const* d_in, const int* in_sizes, int n_in,
                              void* d_out, int out_size) {
    const int*   x   = (const int*)  d_in[0];
    const float* emb = (const float*)d_in[1];
    const float* Wih = (const float*)d_in[2];
    const float* Whh = (const float*)d_in[3];
    const float* bih = (const float*)d_in[4];
    const float* bhh = (const float*)d_in[5];
    const float* h0  = (const float*)d_in[6];
    const float* c0  = (const float*)d_in[7];
    float*       out = (float*)d_out;

    static int attr_set = 0;
    if (!attr_set) {
        cudaFuncSetAttribute(step_all,
                             cudaFuncAttributeMaxDynamicSharedMemorySize,
                             SMEM_BYTES);
        attr_set = 1;
    }

    table_kernel<<<dim3(32, 8), 128>>>(emb, Wih, bih, bhh);
    pack_w_kernel<<<(GG * HH) / 256, 256>>>(Whh);
    init_kernel<<<(BB * HH) / 256, 256>>>(h0);
    step_all<<<NBLK, NTHR, SMEM_BYTES>>>(x, c0, out);
}

// round 8
// speedup vs baseline: 4.2170x; 1.5329x over previous
#include <cuda_runtime.h>
#include <cuda_fp16.h>
#include <math.h>
#include <stdint.h>

// CharsLstm B=64 T=512 E=256 H=1024 V=256 — mma.sync fp16 two-term split.
//
// gates[4096,64] = W @ h,  W = Whi_f16 + Wlo_f16 (exact to 2^-22), h = f16(h).
//   W*h ~= Whi*h + Wlo*h        (error ~ h-quantization 2^-11 per step)
//
// R8: 128 persistent blocks (1/SM) x 512 threads. Block owns 32 gate rows =
// 8 hidden units x 4 gates; Whi/Wlo slices (128KB) resident in SMEM all steps.
// h ping-pong in global f16 [b][k], streamed via cp.async.cg in 4 double-
// buffered 32KB chunks. NO grid barrier: 4 per-chunk monotonic counters;
// producers (32 blocks each) fence+atomicAdd after writing h; consumers
// acquire-poll counter >= 32*t before staging a chunk. 16 warps: 8 m16n16
// output tiles x 2-way split-K, partials reduced via smem. c in registers.

#define BB   64
#define TT   512
#define HH   1024
#define GG   4096
#define NBLK 128
#define NTHR 512

#define WP_B   2064                   // W smem row pitch bytes (1032 halfs)
#define HP_B   528                    // h chunk row pitch bytes (264 halfs)
#define OFF_TOK 0
#define OFF_GS  256
#define OFF_WHI 8704                  // 256 + 32*66*4
#define OFF_WLO (OFF_WHI + 32 * WP_B)
#define OFF_HS0 (OFF_WLO + 32 * WP_B)         // 140800
#define OFF_HS1 (OFF_HS0 + 64 * HP_B)
#define SMEM_BYTES (OFF_HS1 + 64 * HP_B)      // 208384

__device__ __half   g_Whi[GG * HH];           // 8 MB
__device__ __half   g_Wlo[GG * HH];           // 8 MB
__device__ __half   g_h[2][BB * HH];          // ping-pong hidden (f16)
__device__ float    g_table[256 * GG];        // 4 MB
__device__ unsigned g_cnt[4];                 // per-256k-chunk step counters

// ---------------------------------------------------------------- helpers
__device__ __forceinline__ uint32_t smem_u32(const void* p) {
    uint32_t a;
    asm("{ .reg .u64 t; cvta.to.shared.u64 t, %1; cvt.u32.u64 %0, t; }"
        : "=r"(a) : "l"(p));
    return a;
}
__device__ __forceinline__ unsigned ld_acq(const unsigned* p) {
    unsigned v;
    asm volatile("ld.acquire.gpu.global.u32 %0, [%1];" : "=r"(v) : "l"(p));
    return v;
}
#define LDSM4(r0, r1, r2, r3, a)                                            \
    asm volatile("ldmatrix.sync.aligned.m8n8.x4.shared.b16 {%0,%1,%2,%3}, [%4];" \
        : "=r"(r0), "=r"(r1), "=r"(r2), "=r"(r3) : "r"(a))
#define MMA16816(d0, d1, d2, d3, a0, a1, a2, a3, b0, b1)                    \
    asm volatile("mma.sync.aligned.m16n8k16.row.col.f32.f16.f16.f32 "       \
        "{%0,%1,%2,%3}, {%4,%5,%6,%7}, {%8,%9}, {%0,%1,%2,%3};"             \
        : "+f"(d0), "+f"(d1), "+f"(d2), "+f"(d3)                            \
        : "r"(a0), "r"(a1), "r"(a2), "r"(a3), "r"(b0), "r"(b1))
#define CP_ASYNC16(dst, src)                                                \
    asm volatile("cp.async.cg.shared.global [%0], [%1], 16;"                \
        :: "r"(dst), "l"(src) : "memory")
#define CP_COMMIT() asm volatile("cp.async.commit_group;" ::: "memory")
#define CP_WAIT0()  asm volatile("cp.async.wait_group 0;" ::: "memory")

// ---------------------------------------------------------------- setup
__global__ void table_kernel(const float* __restrict__ emb,
                             const float* __restrict__ W_ih,
                             const float* __restrict__ b_ih,
                             const float* __restrict__ b_hh) {
    __shared__ float embs[32 * 65];
    __shared__ float wch[64 * 129];
    const int g  = threadIdx.x;
    const int gt = blockIdx.x, vt = blockIdx.y;
    float acc[32];
#pragma unroll
    for (int v = 0; v < 32; v++) acc[v] = 0.f;

    for (int ch = 0; ch < 4; ch++) {
        __syncthreads();
        for (int i = g; i < 2048; i += 128) {
            int v = i >> 6, e = i & 63;
            embs[v * 65 + e] = emb[(vt * 32 + v) * 256 + ch * 64 + e];
        }
        {
            const float4* src = (const float4*)(W_ih + (size_t)(gt * 128 + g) * 256 + ch * 64);
#pragma unroll
            for (int q = 0; q < 16; q++) {
                float4 w = src[q];
                wch[(q * 4 + 0) * 129 + g] = w.x;
                wch[(q * 4 + 1) * 129 + g] = w.y;
                wch[(q * 4 + 2) * 129 + g] = w.z;
                wch[(q * 4 + 3) * 129 + g] = w.w;
            }
        }
        __syncthreads();
#pragma unroll 4
        for (int e = 0; e < 64; e++) {
            float w = wch[e * 129 + g];
#pragma unroll
            for (int v = 0; v < 32; v++) acc[v] += w * embs[v * 65 + e];
        }
    }
    int col = gt * 128 + g;
    float bias = b_ih[col] + b_hh[col];
#pragma unroll
    for (int v = 0; v < 32; v++) {
        int tok = vt * 32 + v;
        g_table[(size_t)tok * GG + col] = (tok == 0 ? 0.f : acc[v]) + bias;
    }
}

__global__ void pack_w_kernel(const float* __restrict__ Whh) {
    int idx = blockIdx.x * 256 + threadIdx.x;
    float v = Whh[idx];
    __half hi = __float2half(v);
    g_Whi[idx] = hi;
    g_Wlo[idx] = __float2half(v - __half2float(hi));
}

__global__ void init_kernel(const float* __restrict__ h0) {
    int i = blockIdx.x * 256 + threadIdx.x;
    g_h[1][i] = __float2half(h0[i]);          // t=0 reads buffer (0+1)&1 = 1
    if (i < 4) g_cnt[i] = 0;
}

// ---------------------------------------------------------------- main
__global__ void __launch_bounds__(NTHR, 1)
step_all(const int* __restrict__ x,
         const float* __restrict__ c0,
         float* __restrict__ out) {
    extern __shared__ __align__(16) unsigned char sm[];
    const uint32_t smb = smem_u32(sm);
    int*   s_tok = (int*)(sm + OFF_TOK);
    float* gs    = (float*)(sm + OFF_GS);     // [32 rows][pitch 66]

    const int tid   = threadIdx.x;
    const int bid   = blockIdx.x;
    const int lane  = tid & 31;
    const int warp  = tid >> 5;
    const int warpM = warp & 1;               // 2 x m16
    const int warpN = (warp >> 1) & 3;        // 4 x n16
    const int warpK = warp >> 3;              // 2-way split-K
    const int khalf2 = warpK * 256;           // byte offset of 128-k half

    // ---- stage Whi/Wlo slices once (block rows: gate*8 + jj) ----
#pragma unroll
    for (int j = 0; j < 8; j++) {
        int i = j * NTHR + tid;               // 4096 float4 per plane
        int row = i >> 7, q = i & 127;
        int grow = (row >> 3) * HH + bid * 8 + (row & 7);
        *(float4*)(sm + OFF_WHI + row * WP_B + q * 16) =
            __ldcg((const float4*)(g_Whi + (size_t)grow * HH) + q);
        *(float4*)(sm + OFF_WLO + row * WP_B + q * 16) =
            __ldcg((const float4*)(g_Wlo + (size_t)grow * HH) + q);
    }

    // ---- per-lane ldmatrix address bases ----
    const int rowA  = warpM * 16 + (lane & 15);
    const int kOffA = (lane >> 4) * 8;
    const uint32_t aHiBase = smb + OFF_WHI + rowA * WP_B + kOffA * 2 + khalf2;
    const uint32_t aLoBase = smb + OFF_WLO + rowA * WP_B + kOffA * 2 + khalf2;
    const int nB    = warpN * 16 + ((lane >> 4) & 1) * 8 + (lane & 7);
    const int kOffB = ((lane >> 3) & 1) * 8;
    const uint32_t bBase0 = smb + OFF_HS0 + nB * HP_B + kOffB * 2 + khalf2;
    const uint32_t bBase1 = smb + OFF_HS1 + nB * HP_B + kOffB * 2 + khalf2;

    // cell state: 1 cell per thread (unit jj, batch bb)
    const int jj = tid & 7, bb = tid >> 3;
    float creg = c0[bb * HH + bid * 8 + jj];
    const int J  = bid * 8 + jj;
    const int cn = bid >> 5;                  // this block's chunk counter

    __syncthreads();

#pragma unroll 1
    for (int t = 0; t < TT; t++) {
        const __half* __restrict__ hh = g_h[(t + 1) & 1];
        if (tid < BB) s_tok[tid] = x[tid * TT + t];

        float d00=0,d01=0,d02=0,d03=0, d10=0,d11=0,d12=0,d13=0;
        const unsigned need = 32u * (unsigned)t;

        // poll chunk 0 ready, then prefetch chunk 0 -> hs0
        if (t > 0 && tid == 0) { while (ld_acq(&g_cnt[0]) < need) { } }
        __syncthreads();
        {
#pragma unroll
            for (int p = 0; p < 4; p++) {
                int i = p * NTHR + tid;
                int row = i >> 5, kq = i & 31;
                CP_ASYNC16(smb + OFF_HS0 + row * HP_B + kq * 16,
                           hh + row * HH + kq * 8);
            }
            CP_COMMIT();
        }

        // 4 chunks of 256 k, dual-term MMA (Whi + Wlo vs same B)
#pragma unroll 1
        for (int c = 0; c < 4; c++) {
            if (c < 3 && t > 0 && tid == 0) {
                while (ld_acq(&g_cnt[c + 1]) < need) { }
            }
            CP_WAIT0();
            __syncthreads();
            if (c < 3) {
                const __half* src = hh + (c + 1) * 256;
                uint32_t dst = ((c + 1) & 1) ? (smb + OFF_HS1) : (smb + OFF_HS0);
#pragma unroll
                for (int p = 0; p < 4; p++) {
                    int i = p * NTHR + tid;
                    int row = i >> 5, kq = i & 31;
                    CP_ASYNC16(dst + row * HP_B + kq * 16,
                               src + row * HH + kq * 8);
                }
                CP_COMMIT();
            }
            const uint32_t bB = (c & 1) ? bBase1 : bBase0;
            const uint32_t aOff = (uint32_t)c * 512;         // 256 k * 2B
#pragma unroll
            for (int s = 0; s < 8; s++) {
                uint32_t ahi0,ahi1,ahi2,ahi3, alo0,alo1,alo2,alo3, b0,b1,b2,b3;
                LDSM4(ahi0,ahi1,ahi2,ahi3, aHiBase + aOff + s * 32);
                LDSM4(alo0,alo1,alo2,alo3, aLoBase + aOff + s * 32);
                LDSM4(b0,b1,b2,b3, bB + s * 32);
                MMA16816(d00,d01,d02,d03, ahi0,ahi1,ahi2,ahi3, b0,b1);
                MMA16816(d00,d01,d02,d03, alo0,alo1,alo2,alo3, b0,b1);
                MMA16816(d10,d11,d12,d13, ahi0,ahi1,ahi2,ahi3, b2,b3);
                MMA16816(d10,d11,d12,d13, alo0,alo1,alo2,alo3, b2,b3);
            }
        }

        // ---- split-K reduce into gs[row][b] ----
        const int r0  = warpM * 16 + (lane >> 2);
        const int c0i = warpN * 16 + (lane & 3) * 2;
        __syncthreads();
        if (warpK == 1) {
            *(float2*)(gs + (r0    ) * 66 + c0i    ) = make_float2(d00, d01);
            *(float2*)(gs + (r0 + 8) * 66 + c0i    ) = make_float2(d02, d03);
            *(float2*)(gs + (r0    ) * 66 + c0i + 8) = make_float2(d10, d11);
            *(float2*)(gs + (r0 + 8) * 66 + c0i + 8) = make_float2(d12, d13);
        }
        __syncthreads();
        if (warpK == 0) {
            float2* p;
            p = (float2*)(gs + (r0    ) * 66 + c0i    ); p->x += d00; p->y += d01;
            p = (float2*)(gs + (r0 + 8) * 66 + c0i    ); p->x += d02; p->y += d03;
            p = (float2*)(gs + (r0    ) * 66 + c0i + 8); p->x += d10; p->y += d11;
            p = (float2*)(gs + (r0 + 8) * 66 + c0i + 8); p->x += d12; p->y += d13;
        }
        __syncthreads();

        // ---- fused LSTM cell: 1 cell per thread ----
        __half* __restrict__ nh = g_h[t & 1];
        {
            int tok = s_tok[bb];
            const float* trow = g_table + (size_t)tok * GG + J;
            float ipre = gs[(0 * 8 + jj) * 66 + bb] + trow[0];
            float fpre = gs[(1 * 8 + jj) * 66 + bb] + trow[HH];
            float gpre = gs[(2 * 8 + jj) * 66 + bb] + trow[2 * HH];
            float opre = gs[(3 * 8 + jj) * 66 + bb] + trow[3 * HH];
            float isg = 1.f / (1.f + expf(-ipre));
            float fsg = 1.f / (1.f + expf(-fpre));
            float gth = tanhf(gpre);
            float osg = 1.f / (1.f + expf(-opre));
            float cv = fsg * creg + isg * gth;
            creg = cv;
            float hv = osg * tanhf(cv);
            nh[bb * HH + J] = __float2half(hv);
            if (t == TT - 1) out[bb * HH + J] = hv;
        }

        // ---- signal this block's chunk written for step t ----
        __syncthreads();
        if (t < TT - 1 && tid == 0) {
            __threadfence();
            atomicAdd(&g_cnt[cn], 1u);
        }
    }
}

// ---------------------------------------------------------------------------
extern "C" void kernel_launch(void* const* d_in, const int* in_sizes, int n_in,
                              void* d_out, int out_size) {
    const int*   x   = (const int*)  d_in[0];
    const float* emb = (const float*)d_in[1];
    const float* Wih = (const float*)d_in[2];
    const float* Whh = (const float*)d_in[3];
    const float* bih = (const float*)d_in[4];
    const float* bhh = (const float*)d_in[5];
    const float* h0  = (const float*)d_in[6];
    const float* c0  = (const float*)d_in[7];
    float*       out = (float*)d_out;

    static int attr_set = 0;
    if (!attr_set) {
        cudaFuncSetAttribute(step_all,
                             cudaFuncAttributeMaxDynamicSharedMemorySize,
                             SMEM_BYTES);
        attr_set = 1;
    }

    table_kernel<<<dim3(32, 8), 128>>>(emb, Wih, bih, bhh);
    pack_w_kernel<<<(GG * HH) / 256, 256>>>(Whh);
    init_kernel<<<(BB * HH) / 256, 256>>>(h0);
    step_all<<<NBLK, NTHR, SMEM_BYTES>>>(x, c0, out);
}

// round 9
// speedup vs baseline: 4.3804x; 1.0388x over previous
#include <cuda_runtime.h>
#include <cuda_fp16.h>
#include <math.h>
#include <stdint.h>

// CharsLstm B=64 T=512 E=256 H=1024 V=256 — mma.sync fp16 two-term split.
//
// gates[4096,64] = W @ h,  W = Whi_f16 + Wlo_f16 (exact to 2^-22), h = f16(h).
// R9: independent accumulator chains for the hi/lo terms (no RAW-on-accum
// stalls), release-atomic step signal, early table/token prefetch.
// 128 persistent blocks (1/SM) x 512 threads; W slices resident in SMEM;
// h ping-pong f16 in global, cp.async double-buffered 32KB chunks; chunk-
// counter dataflow instead of a grid barrier; c in registers.

#define BB   64
#define TT   512
#define HH   1024
#define GG   4096
#define NBLK 128
#define NTHR 512

#define WP_B   2064                   // W smem row pitch bytes (1032 halfs)
#define HP_B   528                    // h chunk row pitch bytes (264 halfs)
#define OFF_GS  256
#define OFF_WHI 8704                  // 256 + 32*66*4
#define OFF_WLO (OFF_WHI + 32 * WP_B)
#define OFF_HS0 (OFF_WLO + 32 * WP_B)         // 140800
#define OFF_HS1 (OFF_HS0 + 64 * HP_B)
#define SMEM_BYTES (OFF_HS1 + 64 * HP_B)      // 208384

__device__ __half   g_Whi[GG * HH];           // 8 MB
__device__ __half   g_Wlo[GG * HH];           // 8 MB
__device__ __half   g_h[2][BB * HH];          // ping-pong hidden (f16)
__device__ float    g_table[256 * GG];        // 4 MB
__device__ unsigned g_cnt[4];                 // per-256k-chunk step counters

// ---------------------------------------------------------------- helpers
__device__ __forceinline__ uint32_t smem_u32(const void* p) {
    uint32_t a;
    asm("{ .reg .u64 t; cvta.to.shared.u64 t, %1; cvt.u32.u64 %0, t; }"
        : "=r"(a) : "l"(p));
    return a;
}
__device__ __forceinline__ unsigned ld_acq(const unsigned* p) {
    unsigned v;
    asm volatile("ld.acquire.gpu.global.u32 %0, [%1];" : "=r"(v) : "l"(p));
    return v;
}
__device__ __forceinline__ void red_release(unsigned* p, unsigned v) {
    asm volatile("red.release.gpu.global.add.u32 [%0], %1;"
                 :: "l"(p), "r"(v) : "memory");
}
#define LDSM4(r0, r1, r2, r3, a)                                            \
    asm volatile("ldmatrix.sync.aligned.m8n8.x4.shared.b16 {%0,%1,%2,%3}, [%4];" \
        : "=r"(r0), "=r"(r1), "=r"(r2), "=r"(r3) : "r"(a))
#define MMA16816(d0, d1, d2, d3, a0, a1, a2, a3, b0, b1)                    \
    asm volatile("mma.sync.aligned.m16n8k16.row.col.f32.f16.f16.f32 "       \
        "{%0,%1,%2,%3}, {%4,%5,%6,%7}, {%8,%9}, {%0,%1,%2,%3};"             \
        : "+f"(d0), "+f"(d1), "+f"(d2), "+f"(d3)                            \
        : "r"(a0), "r"(a1), "r"(a2), "r"(a3), "r"(b0), "r"(b1))
#define CP_ASYNC16(dst, src)                                                \
    asm volatile("cp.async.cg.shared.global [%0], [%1], 16;"                \
        :: "r"(dst), "l"(src) : "memory")
#define CP_COMMIT() asm volatile("cp.async.commit_group;" ::: "memory")
#define CP_WAIT0()  asm volatile("cp.async.wait_group 0;" ::: "memory")

// ---------------------------------------------------------------- setup
__global__ void table_kernel(const float* __restrict__ emb,
                             const float* __restrict__ W_ih,
                             const float* __restrict__ b_ih,
                             const float* __restrict__ b_hh) {
    __shared__ float embs[32 * 65];
    __shared__ float wch[64 * 129];
    const int g  = threadIdx.x;
    const int gt = blockIdx.x, vt = blockIdx.y;
    float acc[32];
#pragma unroll
    for (int v = 0; v < 32; v++) acc[v] = 0.f;

    for (int ch = 0; ch < 4; ch++) {
        __syncthreads();
        for (int i = g; i < 2048; i += 128) {
            int v = i >> 6, e = i & 63;
            embs[v * 65 + e] = emb[(vt * 32 + v) * 256 + ch * 64 + e];
        }
        {
            const float4* src = (const float4*)(W_ih + (size_t)(gt * 128 + g) * 256 + ch * 64);
#pragma unroll
            for (int q = 0; q < 16; q++) {
                float4 w = src[q];
                wch[(q * 4 + 0) * 129 + g] = w.x;
                wch[(q * 4 + 1) * 129 + g] = w.y;
                wch[(q * 4 + 2) * 129 + g] = w.z;
                wch[(q * 4 + 3) * 129 + g] = w.w;
            }
        }
        __syncthreads();
#pragma unroll 4
        for (int e = 0; e < 64; e++) {
            float w = wch[e * 129 + g];
#pragma unroll
            for (int v = 0; v < 32; v++) acc[v] += w * embs[v * 65 + e];
        }
    }
    int col = gt * 128 + g;
    float bias = b_ih[col] + b_hh[col];
#pragma unroll
    for (int v = 0; v < 32; v++) {
        int tok = vt * 32 + v;
        g_table[(size_t)tok * GG + col] = (tok == 0 ? 0.f : acc[v]) + bias;
    }
}

__global__ void pack_w_kernel(const float* __restrict__ Whh) {
    int idx = blockIdx.x * 256 + threadIdx.x;
    float v = Whh[idx];
    __half hi = __float2half(v);
    g_Whi[idx] = hi;
    g_Wlo[idx] = __float2half(v - __half2float(hi));
}

__global__ void init_kernel(const float* __restrict__ h0) {
    int i = blockIdx.x * 256 + threadIdx.x;
    g_h[1][i] = __float2half(h0[i]);          // t=0 reads buffer (0+1)&1 = 1
    if (i < 4) g_cnt[i] = 0;
}

// ---------------------------------------------------------------- main
__global__ void __launch_bounds__(NTHR, 1)
step_all(const int* __restrict__ x,
         const float* __restrict__ c0,
         float* __restrict__ out) {
    extern __shared__ __align__(16) unsigned char sm[];
    const uint32_t smb = smem_u32(sm);
    float* gs = (float*)(sm + OFF_GS);        // [32 rows][pitch 66]

    const int tid   = threadIdx.x;
    const int bid   = blockIdx.x;
    const int lane  = tid & 31;
    const int warp  = tid >> 5;
    const int warpM = warp & 1;               // 2 x m16
    const int warpN = (warp >> 1) & 3;        // 4 x n16
    const int warpK = warp >> 3;              // 2-way split-K
    const int khalf2 = warpK * 256;           // byte offset of 128-k half

    // ---- stage Whi/Wlo slices once (block rows: gate*8 + jj) ----
#pragma unroll
    for (int j = 0; j < 8; j++) {
        int i = j * NTHR + tid;               // 4096 float4 per plane
        int row = i >> 7, q = i & 127;
        int grow = (row >> 3) * HH + bid * 8 + (row & 7);
        *(float4*)(sm + OFF_WHI + row * WP_B + q * 16) =
            __ldcg((const float4*)(g_Whi + (size_t)grow * HH) + q);
        *(float4*)(sm + OFF_WLO + row * WP_B + q * 16) =
            __ldcg((const float4*)(g_Wlo + (size_t)grow * HH) + q);
    }

    // ---- per-lane ldmatrix address bases ----
    const int rowA  = warpM * 16 + (lane & 15);
    const int kOffA = (lane >> 4) * 8;
    const uint32_t aHiBase = smb + OFF_WHI + rowA * WP_B + kOffA * 2 + khalf2;
    const uint32_t aLoBase = smb + OFF_WLO + rowA * WP_B + kOffA * 2 + khalf2;
    const int nB    = warpN * 16 + ((lane >> 4) & 1) * 8 + (lane & 7);
    const int kOffB = ((lane >> 3) & 1) * 8;
    const uint32_t bBase0 = smb + OFF_HS0 + nB * HP_B + kOffB * 2 + khalf2;
    const uint32_t bBase1 = smb + OFF_HS1 + nB * HP_B + kOffB * 2 + khalf2;

    // cell state: 1 cell per thread (unit jj, batch bb)
    const int jj = tid & 7, bb = tid >> 3;
    float creg = c0[bb * HH + bid * 8 + jj];
    const int J  = bid * 8 + jj;
    const int cn = bid >> 5;                  // this block's chunk counter

    __syncthreads();

#pragma unroll 1
    for (int t = 0; t < TT; t++) {
        const __half* __restrict__ hh = g_h[(t + 1) & 1];

        // early per-thread prefetch: token + the 4 table entries for the cell
        const int tok = __ldg(&x[bb * TT + t]);
        const float* trow = g_table + (size_t)tok * GG + J;
        float tb0 = __ldg(trow);
        float tb1 = __ldg(trow + HH);
        float tb2 = __ldg(trow + 2 * HH);
        float tb3 = __ldg(trow + 3 * HH);

        // independent accumulator chains: hi term + lo term
        float h00=0,h01=0,h02=0,h03=0, h10=0,h11=0,h12=0,h13=0;
        float l00=0,l01=0,l02=0,l03=0, l10=0,l11=0,l12=0,l13=0;
        const unsigned need = 32u * (unsigned)t;

        // poll chunk 0 ready, then prefetch chunk 0 -> hs0
        if (t > 0 && tid == 0) { while (ld_acq(&g_cnt[0]) < need) { } }
        __syncthreads();
        {
#pragma unroll
            for (int p = 0; p < 4; p++) {
                int i = p * NTHR + tid;
                int row = i >> 5, kq = i & 31;
                CP_ASYNC16(smb + OFF_HS0 + row * HP_B + kq * 16,
                           hh + row * HH + kq * 8);
            }
            CP_COMMIT();
        }

        // 4 chunks of 256 k, dual-term MMA with separate accumulators
#pragma unroll 1
        for (int c = 0; c < 4; c++) {
            if (c < 3 && t > 0 && tid == 0) {
                while (ld_acq(&g_cnt[c + 1]) < need) { }
            }
            CP_WAIT0();
            __syncthreads();
            if (c < 3) {
                const __half* src = hh + (c + 1) * 256;
                uint32_t dst = ((c + 1) & 1) ? (smb + OFF_HS1) : (smb + OFF_HS0);
#pragma unroll
                for (int p = 0; p < 4; p++) {
                    int i = p * NTHR + tid;
                    int row = i >> 5, kq = i & 31;
                    CP_ASYNC16(dst + row * HP_B + kq * 16,
                               src + row * HH + kq * 8);
                }
                CP_COMMIT();
            }
            const uint32_t bB = (c & 1) ? bBase1 : bBase0;
            const uint32_t aOff = (uint32_t)c * 512;         // 256 k * 2B
#pragma unroll
            for (int s = 0; s < 8; s++) {
                uint32_t a0,a1,a2,a3, e0,e1,e2,e3, b0,b1,b2,b3;
                LDSM4(a0,a1,a2,a3, aHiBase + aOff + s * 32);
                LDSM4(e0,e1,e2,e3, aLoBase + aOff + s * 32);
                LDSM4(b0,b1,b2,b3, bB + s * 32);
                MMA16816(h00,h01,h02,h03, a0,a1,a2,a3, b0,b1);
                MMA16816(l00,l01,l02,l03, e0,e1,e2,e3, b0,b1);
                MMA16816(h10,h11,h12,h13, a0,a1,a2,a3, b2,b3);
                MMA16816(l10,l11,l12,l13, e0,e1,e2,e3, b2,b3);
            }
        }

        // merge term chains
        float d00=h00+l00, d01=h01+l01, d02=h02+l02, d03=h03+l03;
        float d10=h10+l10, d11=h11+l11, d12=h12+l12, d13=h13+l13;

        // ---- split-K reduce into gs[row][b] ----
        const int r0  = warpM * 16 + (lane >> 2);
        const int c0i = warpN * 16 + (lane & 3) * 2;
        if (warpK == 1) {
            *(float2*)(gs + (r0    ) * 66 + c0i    ) = make_float2(d00, d01);
            *(float2*)(gs + (r0 + 8) * 66 + c0i    ) = make_float2(d02, d03);
            *(float2*)(gs + (r0    ) * 66 + c0i + 8) = make_float2(d10, d11);
            *(float2*)(gs + (r0 + 8) * 66 + c0i + 8) = make_float2(d12, d13);
        }
        __syncthreads();
        if (warpK == 0) {
            float2* p;
            p = (float2*)(gs + (r0    ) * 66 + c0i    ); p->x += d00; p->y += d01;
            p = (float2*)(gs + (r0 + 8) * 66 + c0i    ); p->x += d02; p->y += d03;
            p = (float2*)(gs + (r0    ) * 66 + c0i + 8); p->x += d10; p->y += d11;
            p = (float2*)(gs + (r0 + 8) * 66 + c0i + 8); p->x += d12; p->y += d13;
        }
        __syncthreads();

        // ---- fused LSTM cell: 1 cell per thread ----
        __half* __restrict__ nh = g_h[t & 1];
        {
            float ipre = gs[(0 * 8 + jj) * 66 + bb] + tb0;
            float fpre = gs[(1 * 8 + jj) * 66 + bb] + tb1;
            float gpre = gs[(2 * 8 + jj) * 66 + bb] + tb2;
            float opre = gs[(3 * 8 + jj) * 66 + bb] + tb3;
            float isg = 1.f / (1.f + expf(-ipre));
            float fsg = 1.f / (1.f + expf(-fpre));
            float gth = tanhf(gpre);
            float osg = 1.f / (1.f + expf(-opre));
            float cv = fsg * creg + isg * gth;
            creg = cv;
            float hv = osg * tanhf(cv);
            nh[bb * HH + J] = __float2half(hv);
            if (t == TT - 1) out[bb * HH + J] = hv;
        }

        // ---- signal this block's chunk written for step t (release) ----
        __syncthreads();
        if (t < TT - 1 && tid == 0) {
            red_release(&g_cnt[cn], 1u);
        }
    }
}

// ---------------------------------------------------------------------------
extern "C" void kernel_launch(void* const* d_in, const int* in_sizes, int n_in,
                              void* d_out, int out_size) {
    const int*   x   = (const int*)  d_in[0];
    const float* emb = (const float*)d_in[1];
    const float* Wih = (const float*)d_in[2];
    const float* Whh = (const float*)d_in[3];
    const float* bih = (const float*)d_in[4];
    const float* bhh = (const float*)d_in[5];
    const float* h0  = (const float*)d_in[6];
    const float* c0  = (const float*)d_in[7];
    float*       out = (float*)d_out;

    static int attr_set = 0;
    if (!attr_set) {
        cudaFuncSetAttribute(step_all,
                             cudaFuncAttributeMaxDynamicSharedMemorySize,
                             SMEM_BYTES);
        attr_set = 1;
    }

    table_kernel<<<dim3(32, 8), 128>>>(emb, Wih, bih, bhh);
    pack_w_kernel<<<(GG * HH) / 256, 256>>>(Whh);
    init_kernel<<<(BB * HH) / 256, 256>>>(h0);
    step_all<<<NBLK, NTHR, SMEM_BYTES>>>(x, c0, out);
}

// round 11
// speedup vs baseline: 4.5063x; 1.0287x over previous
#include <cuda_runtime.h>
#include <cuda_fp16.h>
#include <math.h>
#include <stdint.h>

// CharsLstm B=64 T=512 E=256 H=1024 V=256 — mma.sync fp16 two-term split.
//
// gates[4096,64] = W @ h,  W = Whi_f16 + Wlo_f16 (exact to 2^-22), h = f16(h).
// R11 (= R10 resubmit after infra failure): hardware activations
// (ex2/rcp/tanh.approx) to shrink the serial epilogue; rotated per-block
// chunk schedule to decorrelate the inter-block handshake and spread the
// L2 burst. GEMM core unchanged from R9.
// 128 persistent blocks (1/SM) x 512 threads; W slices resident in SMEM;
// h ping-pong f16 in global, cp.async double-buffered 32KB chunks; chunk-
// counter dataflow (no grid barrier); c in registers.

#define BB   64
#define TT   512
#define HH   1024
#define GG   4096
#define NBLK 128
#define NTHR 512

#define WP_B   2064                   // W smem row pitch bytes (1032 halfs)
#define HP_B   528                    // h chunk row pitch bytes (264 halfs)
#define OFF_GS  256
#define OFF_WHI 8704                  // 256 + 32*66*4
#define OFF_WLO (OFF_WHI + 32 * WP_B)
#define OFF_HS0 (OFF_WLO + 32 * WP_B)         // 140800
#define OFF_HS1 (OFF_HS0 + 64 * HP_B)
#define SMEM_BYTES (OFF_HS1 + 64 * HP_B)      // 208384

__device__ __half   g_Whi[GG * HH];           // 8 MB
__device__ __half   g_Wlo[GG * HH];           // 8 MB
__device__ __half   g_h[2][BB * HH];          // ping-pong hidden (f16)
__device__ float    g_table[256 * GG];        // 4 MB
__device__ unsigned g_cnt[4];                 // per-256k-chunk step counters

// ---------------------------------------------------------------- helpers
__device__ __forceinline__ uint32_t smem_u32(const void* p) {
    uint32_t a;
    asm("{ .reg .u64 t; cvta.to.shared.u64 t, %1; cvt.u32.u64 %0, t; }"
        : "=r"(a) : "l"(p));
    return a;
}
__device__ __forceinline__ unsigned ld_acq(const unsigned* p) {
    unsigned v;
    asm volatile("ld.acquire.gpu.global.u32 %0, [%1];" : "=r"(v) : "l"(p));
    return v;
}
__device__ __forceinline__ void red_release(unsigned* p, unsigned v) {
    asm volatile("red.release.gpu.global.add.u32 [%0], %1;"
                 :: "l"(p), "r"(v) : "memory");
}
__device__ __forceinline__ float fast_sigmoid(float v) {
    float e, r;
    asm("ex2.approx.f32 %0, %1;" : "=f"(e) : "f"(v * -1.4426950408889634f));
    asm("rcp.approx.f32 %0, %1;" : "=f"(r) : "f"(1.f + e));
    return r;
}
__device__ __forceinline__ float fast_tanh(float v) {
    float r;
    asm("tanh.approx.f32 %0, %1;" : "=f"(r) : "f"(v));
    return r;
}
#define LDSM4(r0, r1, r2, r3, a)                                            \
    asm volatile("ldmatrix.sync.aligned.m8n8.x4.shared.b16 {%0,%1,%2,%3}, [%4];" \
        : "=r"(r0), "=r"(r1), "=r"(r2), "=r"(r3) : "r"(a))
#define MMA16816(d0, d1, d2, d3, a0, a1, a2, a3, b0, b1)                    \
    asm volatile("mma.sync.aligned.m16n8k16.row.col.f32.f16.f16.f32 "       \
        "{%0,%1,%2,%3}, {%4,%5,%6,%7}, {%8,%9}, {%0,%1,%2,%3};"             \
        : "+f"(d0), "+f"(d1), "+f"(d2), "+f"(d3)                            \
        : "r"(a0), "r"(a1), "r"(a2), "r"(a3), "r"(b0), "r"(b1))
#define CP_ASYNC16(dst, src)                                                \
    asm volatile("cp.async.cg.shared.global [%0], [%1], 16;"                \
        :: "r"(dst), "l"(src) : "memory")
#define CP_COMMIT() asm volatile("cp.async.commit_group;" ::: "memory")
#define CP_WAIT0()  asm volatile("cp.async.wait_group 0;" ::: "memory")

// ---------------------------------------------------------------- setup
__global__ void table_kernel(const float* __restrict__ emb,
                             const float* __restrict__ W_ih,
                             const float* __restrict__ b_ih,
                             const float* __restrict__ b_hh) {
    __shared__ float embs[32 * 65];
    __shared__ float wch[64 * 129];
    const int g  = threadIdx.x;
    const int gt = blockIdx.x, vt = blockIdx.y;
    float acc[32];
#pragma unroll
    for (int v = 0; v < 32; v++) acc[v] = 0.f;

    for (int ch = 0; ch < 4; ch++) {
        __syncthreads();
        for (int i = g; i < 2048; i += 128) {
            int v = i >> 6, e = i & 63;
            embs[v * 65 + e] = emb[(vt * 32 + v) * 256 + ch * 64 + e];
        }
        {
            const float4* src = (const float4*)(W_ih + (size_t)(gt * 128 + g) * 256 + ch * 64);
#pragma unroll
            for (int q = 0; q < 16; q++) {
                float4 w = src[q];
                wch[(q * 4 + 0) * 129 + g] = w.x;
                wch[(q * 4 + 1) * 129 + g] = w.y;
                wch[(q * 4 + 2) * 129 + g] = w.z;
                wch[(q * 4 + 3) * 129 + g] = w.w;
            }
        }
        __syncthreads();
#pragma unroll 4
        for (int e = 0; e < 64; e++) {
            float w = wch[e * 129 + g];
#pragma unroll
            for (int v = 0; v < 32; v++) acc[v] += w * embs[v * 65 + e];
        }
    }
    int col = gt * 128 + g;
    float bias = b_ih[col] + b_hh[col];
#pragma unroll
    for (int v = 0; v < 32; v++) {
        int tok = vt * 32 + v;
        g_table[(size_t)tok * GG + col] = (tok == 0 ? 0.f : acc[v]) + bias;
    }
}

__global__ void pack_w_kernel(const float* __restrict__ Whh) {
    int idx = blockIdx.x * 256 + threadIdx.x;
    float v = Whh[idx];
    __half hi = __float2half(v);
    g_Whi[idx] = hi;
    g_Wlo[idx] = __float2half(v - __half2float(hi));
}

__global__ void init_kernel(const float* __restrict__ h0) {
    int i = blockIdx.x * 256 + threadIdx.x;
    g_h[1][i] = __float2half(h0[i]);          // t=0 reads buffer (0+1)&1 = 1
    if (i < 4) g_cnt[i] = 0;
}

// ---------------------------------------------------------------- main
__global__ void __launch_bounds__(NTHR, 1)
step_all(const int* __restrict__ x,
         const float* __restrict__ c0,
         float* __restrict__ out) {
    extern __shared__ __align__(16) unsigned char sm[];
    const uint32_t smb = smem_u32(sm);
    float* gs = (float*)(sm + OFF_GS);        // [32 rows][pitch 66]

    const int tid   = threadIdx.x;
    const int bid   = blockIdx.x;
    const int lane  = tid & 31;
    const int warp  = tid >> 5;
    const int warpM = warp & 1;               // 2 x m16
    const int warpN = (warp >> 1) & 3;        // 4 x n16
    const int warpK = warp >> 3;              // 2-way split-K
    const int khalf2 = warpK * 256;           // byte offset of 128-k half

    // ---- stage Whi/Wlo slices once (block rows: gate*8 + jj) ----
#pragma unroll
    for (int j = 0; j < 8; j++) {
        int i = j * NTHR + tid;               // 4096 float4 per plane
        int row = i >> 7, q = i & 127;
        int grow = (row >> 3) * HH + bid * 8 + (row & 7);
        *(float4*)(sm + OFF_WHI + row * WP_B + q * 16) =
            __ldcg((const float4*)(g_Whi + (size_t)grow * HH) + q);
        *(float4*)(sm + OFF_WLO + row * WP_B + q * 16) =
            __ldcg((const float4*)(g_Wlo + (size_t)grow * HH) + q);
    }

    // ---- per-lane ldmatrix address bases ----
    const int rowA  = warpM * 16 + (lane & 15);
    const int kOffA = (lane >> 4) * 8;
    const uint32_t aHiBase = smb + OFF_WHI + rowA * WP_B + kOffA * 2 + khalf2;
    const uint32_t aLoBase = smb + OFF_WLO + rowA * WP_B + kOffA * 2 + khalf2;
    const int nB    = warpN * 16 + ((lane >> 4) & 1) * 8 + (lane & 7);
    const int kOffB = ((lane >> 3) & 1) * 8;
    const uint32_t bBase0 = smb + OFF_HS0 + nB * HP_B + kOffB * 2 + khalf2;
    const uint32_t bBase1 = smb + OFF_HS1 + nB * HP_B + kOffB * 2 + khalf2;

    // cell state: 1 cell per thread (unit jj, batch bb)
    const int jj = tid & 7, bb = tid >> 3;
    float creg = c0[bb * HH + bid * 8 + jj];
    const int J  = bid * 8 + jj;
    const int cn = bid >> 5;                  // this block's producer chunk

    __syncthreads();

#pragma unroll 1
    for (int t = 0; t < TT; t++) {
        const __half* __restrict__ hh = g_h[(t + 1) & 1];

        // early per-thread prefetch: token + the 4 table entries for the cell
        const int tok = __ldg(&x[bb * TT + t]);
        const float* trow = g_table + (size_t)tok * GG + J;
        float tb0 = __ldg(trow);
        float tb1 = __ldg(trow + HH);
        float tb2 = __ldg(trow + 2 * HH);
        float tb3 = __ldg(trow + 3 * HH);

        // independent accumulator chains: hi term + lo term
        float h00=0,h01=0,h02=0,h03=0, h10=0,h11=0,h12=0,h13=0;
        float l00=0,l01=0,l02=0,l03=0, l10=0,l11=0,l12=0,l13=0;
        const unsigned need = 32u * (unsigned)t;

        // rotated schedule: consume chunks cn, cn+1, cn+2, cn+3 (mod 4)
        if (t > 0 && tid == 0) { while (ld_acq(&g_cnt[cn]) < need) { } }
        __syncthreads();
        {   // prefetch first chunk (cn) -> hs0
            const __half* src = hh + cn * 256;
#pragma unroll
            for (int p = 0; p < 4; p++) {
                int i = p * NTHR + tid;
                int row = i >> 5, kq = i & 31;
                CP_ASYNC16(smb + OFF_HS0 + row * HP_B + kq * 16,
                           src + row * HH + kq * 8);
            }
            CP_COMMIT();
        }

#pragma unroll 1
        for (int i4 = 0; i4 < 4; i4++) {
            const int cnext = (cn + i4 + 1) & 3;
            if (i4 < 3 && t > 0 && tid == 0) {
                while (ld_acq(&g_cnt[cnext]) < need) { }
            }
            CP_WAIT0();
            __syncthreads();
            if (i4 < 3) {
                const __half* src = hh + cnext * 256;
                uint32_t dst = ((i4 + 1) & 1) ? (smb + OFF_HS1) : (smb + OFF_HS0);
#pragma unroll
                for (int p = 0; p < 4; p++) {
                    int i = p * NTHR + tid;
                    int row = i >> 5, kq = i & 31;
                    CP_ASYNC16(dst + row * HP_B + kq * 16,
                               src + row * HH + kq * 8);
                }
                CP_COMMIT();
            }
            const uint32_t bB = (i4 & 1) ? bBase1 : bBase0;
            const uint32_t aOff = (uint32_t)((cn + i4) & 3) * 512;  // k*2B
#pragma unroll
            for (int s = 0; s < 8; s++) {
                uint32_t a0,a1,a2,a3, e0,e1,e2,e3, b0,b1,b2,b3;
                LDSM4(a0,a1,a2,a3, aHiBase + aOff + s * 32);
                LDSM4(e0,e1,e2,e3, aLoBase + aOff + s * 32);
                LDSM4(b0,b1,b2,b3, bB + s * 32);
                MMA16816(h00,h01,h02,h03, a0,a1,a2,a3, b0,b1);
                MMA16816(l00,l01,l02,l03, e0,e1,e2,e3, b0,b1);
                MMA16816(h10,h11,h12,h13, a0,a1,a2,a3, b2,b3);
                MMA16816(l10,l11,l12,l13, e0,e1,e2,e3, b2,b3);
            }
        }

        // merge term chains
        float d00=h00+l00, d01=h01+l01, d02=h02+l02, d03=h03+l03;
        float d10=h10+l10, d11=h11+l11, d12=h12+l12, d13=h13+l13;

        // ---- split-K reduce into gs[row][b] ----
        const int r0  = warpM * 16 + (lane >> 2);
        const int c0i = warpN * 16 + (lane & 3) * 2;
        if (warpK == 1) {
            *(float2*)(gs + (r0    ) * 66 + c0i    ) = make_float2(d00, d01);
            *(float2*)(gs + (r0 + 8) * 66 + c0i    ) = make_float2(d02, d03);
            *(float2*)(gs + (r0    ) * 66 + c0i + 8) = make_float2(d10, d11);
            *(float2*)(gs + (r0 + 8) * 66 + c0i + 8) = make_float2(d12, d13);
        }
        __syncthreads();
        if (warpK == 0) {
            float2* p;
            p = (float2*)(gs + (r0    ) * 66 + c0i    ); p->x += d00; p->y += d01;
            p = (float2*)(gs + (r0 + 8) * 66 + c0i    ); p->x += d02; p->y += d03;
            p = (float2*)(gs + (r0    ) * 66 + c0i + 8); p->x += d10; p->y += d11;
            p = (float2*)(gs + (r0 + 8) * 66 + c0i + 8); p->x += d12; p->y += d13;
        }
        __syncthreads();

        // ---- fused LSTM cell: 1 cell per thread (HW activations) ----
        __half* __restrict__ nh = g_h[t & 1];
        {
            float ipre = gs[(0 * 8 + jj) * 66 + bb] + tb0;
            float fpre = gs[(1 * 8 + jj) * 66 + bb] + tb1;
            float gpre = gs[(2 * 8 + jj) * 66 + bb] + tb2;
            float opre = gs[(3 * 8 + jj) * 66 + bb] + tb3;
            float isg = fast_sigmoid(ipre);
            float fsg = fast_sigmoid(fpre);
            float gth = fast_tanh(gpre);
            float osg = fast_sigmoid(opre);
            float cv = fsg * creg + isg * gth;
            creg = cv;
            float hv = osg * fast_tanh(cv);
            nh[bb * HH + J] = __float2half(hv);
            if (t == TT - 1) out[bb * HH + J] = hv;
        }

        // ---- signal this block's chunk written for step t (release) ----
        __syncthreads();
        if (t < TT - 1 && tid == 0) {
            red_release(&g_cnt[cn], 1u);
        }
    }
}

// ---------------------------------------------------------------------------
extern "C" void kernel_launch(void* const* d_in, const int* in_sizes, int n_in,
                              void* d_out, int out_size) {
    const int*   x   = (const int*)  d_in[0];
    const float* emb = (const float*)d_in[1];
    const float* Wih = (const float*)d_in[2];
    const float* Whh = (const float*)d_in[3];
    const float* bih = (const float*)d_in[4];
    const float* bhh = (const float*)d_in[5];
    const float* h0  = (const float*)d_in[6];
    const float* c0  = (const float*)d_in[7];
    float*       out = (float*)d_out;

    static int attr_set = 0;
    if (!attr_set) {
        cudaFuncSetAttribute(step_all,
                             cudaFuncAttributeMaxDynamicSharedMemorySize,
                             SMEM_BYTES);
        attr_set = 1;
    }

    table_kernel<<<dim3(32, 8), 128>>>(emb, Wih, bih, bhh);
    pack_w_kernel<<<(GG * HH) / 256, 256>>>(Whh);
    init_kernel<<<(BB * HH) / 256, 256>>>(h0);
    step_all<<<NBLK, NTHR, SMEM_BYTES>>>(x, c0, out);
}